// round 10
// baseline (speedup 1.0000x reference)
#include <cuda_runtime.h>
#include <cstdint>

// Problem constants (fixed shapes)
#define B_  2
#define N_  6
#define Q_  900
#define C_  256
#define H_  116
#define W_  200
#define HW_ (H_ * W_)       // 23200, divisible by 4
#define EPS_ 1e-5f
#define BQ_ (B_ * Q_)       // 1800

// Scratch (no dynamic allocation allowed)
__device__ float g_agg[BQ_ * C_];   // mean-aggregated features

// Uniform-index select from float4 (s is warp-uniform -> predicated SELs)
__device__ __forceinline__ float sel4(float4 f, int s) {
    float v = f.x;
    if (s == 1) v = f.y;
    else if (s == 2) v = f.z;
    else if (s == 3) v = f.w;
    return v;
}

// packed f32x2 fma: d = a*b + d elementwise on (lo,hi) pairs in 64-bit regs
__device__ __forceinline__ void ffma2(unsigned long long& d,
                                      unsigned long long a,
                                      unsigned long long b) {
    asm("fma.rn.f32x2 %0, %1, %2, %0;" : "+l"(d) : "l"(a), "l"(b));
}

// ---------------------------------------------------------------------------
// Fused kernel: projection (threads 0..5) + bilinear gather + camera mean
// one block per (b,q); 64 threads; 4 channels/thread (tid,+64,+128,+192)
// [identical to the R6/R9 best-known gather]
// ---------------------------------------------------------------------------
__global__ __launch_bounds__(64) void gather_kernel(
    const float* __restrict__ feats,     // (B,N,C,H,W)
    const float* __restrict__ ref_pts,   // (B,Q,3)
    const float* __restrict__ lidar2img) // (B,N,4,4)
{
    __shared__ float4 sw[N_];   // weights: (wl_top, wr_top, wl_bot, wr_bot) * valid/N
    __shared__ int4   sb[N_];   // {base_top, base_bot, s0|(s1<<8), valid}

    int bq  = blockIdx.x;       // 0..1799
    int b   = bq / Q_;
    int q   = bq % Q_;
    int tid = threadIdx.x;      // 0..63

    if (tid < N_) {
        int n = tid;
        const float* rp = ref_pts + ((size_t)b * Q_ + q) * 3;
        float px = rp[0], py = rp[1], pz = rp[2];

        const float* M = lidar2img + ((size_t)b * N_ + n) * 16;
        float xc = M[0]  * px + M[1]  * py + M[2]  * pz + M[3];
        float yc = M[4]  * px + M[5]  * py + M[6]  * pz + M[7];
        float zc = M[8]  * px + M[9]  * py + M[10] * pz + M[11];

        float denom = fabsf(zc) + EPS_;
        float x2d = xc / denom;
        float y2d = yc / denom;

        float gx = x2d / (float)(W_ - 1) * 2.0f - 1.0f;
        float gy = y2d / (float)(H_ - 1) * 2.0f - 1.0f;

        bool front  = zc > EPS_;
        bool in_img = fmaxf(fabsf(gx), fabsf(gy)) <= 1.0f;
        int  valid  = (front && in_img) ? 1 : 0;
        float vv    = valid ? (1.0f / (float)N_) : 0.0f;

        float x = ((gx + 1.0f) * (float)W_ - 1.0f) * 0.5f;
        float y = ((gy + 1.0f) * (float)H_ - 1.0f) * 0.5f;
        x = fminf(fmaxf(x, -100.0f), (float)(W_ + 100));
        y = fminf(fmaxf(y, -100.0f), (float)(H_ + 100));

        float x0f = floorf(x), y0f = floorf(y);
        float wx = x - x0f, wy = y - y0f;
        int x0 = (int)x0f, y0 = (int)y0f;
        int x1 = x0 + 1,   y1 = y0 + 1;

        float v00 = (x0 >= 0 && x0 < W_ && y0 >= 0 && y0 < H_) ? 1.0f : 0.0f;
        float v10 = (x1 >= 0 && x1 < W_ && y0 >= 0 && y0 < H_) ? 1.0f : 0.0f;
        float v01 = (x0 >= 0 && x0 < W_ && y1 >= 0 && y1 < H_) ? 1.0f : 0.0f;
        float v11 = (x1 >= 0 && x1 < W_ && y1 >= 0 && y1 < H_) ? 1.0f : 0.0f;

        float4 w;
        w.x = (1.0f - wx) * (1.0f - wy) * v00 * vv;
        w.y = wx          * (1.0f - wy) * v10 * vv;
        w.z = (1.0f - wx) * wy          * v01 * vv;
        w.w = wx          * wy          * v11 * vv;

        int cx0 = min(max(x0, 0), W_ - 1);
        int cx1 = min(max(x1, 0), W_ - 1);
        int cy0 = min(max(y0, 0), H_ - 1);
        int cy1 = min(max(y1, 0), H_ - 1);

        int i0 = cy0 * W_ + cx0;
        int i1 = cy0 * W_ + cx1;
        int j0 = cy1 * W_ + cx0;

        int base_t = i0 & ~3;
        int s0 = i0 - base_t;
        int s1 = i1 - base_t;
        int base_b = j0 - s0;

        sw[n] = w;
        sb[n] = make_int4(base_t, base_b, s0 | (s1 << 8), valid);
    }
    __syncthreads();

    float acc0 = 0.0f;   // channel tid
    float acc1 = 0.0f;   // channel tid + 64
    float acc2 = 0.0f;   // channel tid + 128
    float acc3 = 0.0f;   // channel tid + 192
#pragma unroll
    for (int n = 0; n < N_; n++) {
        int4 ib = sb[n];
        if (!ib.w) continue;            // uniform branch: camera invalid
        float4 w = sw[n];
        const float* p0 = feats + ((size_t)((b * N_ + n) * C_) + tid) * HW_;
        const float* p1 = p0 + (size_t)64  * HW_;
        const float* p2 = p0 + (size_t)128 * HW_;
        const float* p3 = p0 + (size_t)192 * HW_;

        // issue all 8 independent 16B loads before consuming
        float4 t0 = *reinterpret_cast<const float4*>(p0 + ib.x);
        float4 b0v = *reinterpret_cast<const float4*>(p0 + ib.y);
        float4 t1 = *reinterpret_cast<const float4*>(p1 + ib.x);
        float4 b1v = *reinterpret_cast<const float4*>(p1 + ib.y);
        float4 t2 = *reinterpret_cast<const float4*>(p2 + ib.x);
        float4 b2v = *reinterpret_cast<const float4*>(p2 + ib.y);
        float4 t3 = *reinterpret_cast<const float4*>(p3 + ib.x);
        float4 b3v = *reinterpret_cast<const float4*>(p3 + ib.y);

        int s0 = ib.z & 0xff;
        int s1 = ib.z >> 8;

        float vt0a = sel4(t0, s0), vb0a = sel4(b0v, s0);
        float vt0b = sel4(t1, s0), vb0b = sel4(b1v, s0);
        float vt0c = sel4(t2, s0), vb0c = sel4(b2v, s0);
        float vt0d = sel4(t3, s0), vb0d = sel4(b3v, s0);
        float vt1a, vb1a, vt1b, vb1b, vt1c, vb1c, vt1d, vb1d;
        if (s1 < 4) {                   // uniform branch (75% taken)
            vt1a = sel4(t0, s1);  vb1a = sel4(b0v, s1);
            vt1b = sel4(t1, s1);  vb1b = sel4(b1v, s1);
            vt1c = sel4(t2, s1);  vb1c = sel4(b2v, s1);
            vt1d = sel4(t3, s1);  vb1d = sel4(b3v, s1);
        } else {                        // right pixel spills into next float4
            vt1a = __ldg(p0 + ib.x + 4);  vb1a = __ldg(p0 + ib.y + 4);
            vt1b = __ldg(p1 + ib.x + 4);  vb1b = __ldg(p1 + ib.y + 4);
            vt1c = __ldg(p2 + ib.x + 4);  vb1c = __ldg(p2 + ib.y + 4);
            vt1d = __ldg(p3 + ib.x + 4);  vb1d = __ldg(p3 + ib.y + 4);
        }
        acc0 = fmaf(w.x, vt0a, acc0);
        acc0 = fmaf(w.y, vt1a, acc0);
        acc0 = fmaf(w.z, vb0a, acc0);
        acc0 = fmaf(w.w, vb1a, acc0);
        acc1 = fmaf(w.x, vt0b, acc1);
        acc1 = fmaf(w.y, vt1b, acc1);
        acc1 = fmaf(w.z, vb0b, acc1);
        acc1 = fmaf(w.w, vb1b, acc1);
        acc2 = fmaf(w.x, vt0c, acc2);
        acc2 = fmaf(w.y, vt1c, acc2);
        acc2 = fmaf(w.z, vb0c, acc2);
        acc2 = fmaf(w.w, vb1c, acc2);
        acc3 = fmaf(w.x, vt0d, acc3);
        acc3 = fmaf(w.y, vt1d, acc3);
        acc3 = fmaf(w.z, vb0d, acc3);
        acc3 = fmaf(w.w, vb1d, acc3);
    }
    float* outp = &g_agg[(size_t)bq * C_ + tid];
    outp[0]   = acc0;
    outp[64]  = acc1;
    outp[128] = acc2;
    outp[192] = acc3;
}

// ---------------------------------------------------------------------------
// Single-pass GEMM: out = agg @ W^T + bias   (M=1800, N=256, K=256)
// 32x32 tiles (grid 57x8 = 456 blocks), BK=16, 16 double-buffered tiles,
// 256 threads: warps 0-3 load A, warps 4-7 load B. 2x2 microtile, f32x2.
// A duplicated in smem for conflict-free packed fragments; bias in epilogue.
// ---------------------------------------------------------------------------
#define BM 32
#define BN 32
#define BK 16
#define NTILES (C_ / BK)   // 16

__global__ __launch_bounds__(256) void gemm_kernel(const float* __restrict__ Wm,   // (256,256) row-major
                                                   const float* __restrict__ bias,
                                                   float* __restrict__ out)        // (1800,256)
{
    __shared__ float AsDup[2][BK][BM * 2];   // 8 KB: (a,a) pairs per row
    __shared__ float Bs[2][BK][BN];          // 4 KB

    const int M = BQ_;
    int t  = threadIdx.x;
    int tm = t / 16;   // 0..15 -> 2 rows each
    int tn = t % 16;   // 0..15 -> 2 cols each

    int bM = blockIdx.x * BM;
    int bN = blockIdx.y * BN;

    // loader role: warps 0-3 -> A tile, warps 4-7 -> B tile
    bool isA = t < 128;
    int  u   = isA ? t : (t - 128);
    int  lrow = u >> 2;          // 0..31
    int  lk   = (u & 3) * 4;     // 0,4,8,12

    const float* Gptr = isA ? &g_agg[(size_t)(bM + lrow) * C_ + lk]
                            : &Wm[(size_t)(bN + lrow) * C_ + lk];
    bool ok = isA ? ((bM + lrow) < M) : true;

    // accumulators: 2 rows x 1 col-pair; acc2[r] = (c[r][2tn], c[r][2tn+1])
    unsigned long long acc2[2] = {0ull, 0ull};

    // prologue: load tile 0
    float4 v = make_float4(0.f, 0.f, 0.f, 0.f);
    if (ok) v = *reinterpret_cast<const float4*>(Gptr);
    if (isA) {
        float* ad = &AsDup[0][0][0];
        float vv[4] = {v.x, v.y, v.z, v.w};
#pragma unroll
        for (int i = 0; i < 4; i++)
            *reinterpret_cast<float2*>(&ad[(lk + i) * (BM * 2) + lrow * 2]) =
                make_float2(vv[i], vv[i]);
    } else {
        Bs[0][lk + 0][lrow] = v.x;
        Bs[0][lk + 1][lrow] = v.y;
        Bs[0][lk + 2][lrow] = v.z;
        Bs[0][lk + 3][lrow] = v.w;
    }
    __syncthreads();

#pragma unroll
    for (int tile = 0; tile < NTILES; tile++) {
        int cur = tile & 1;
        int nxt = cur ^ 1;

        // prefetch next tile gmem -> regs
        if (tile + 1 < NTILES) {
            v = make_float4(0.f, 0.f, 0.f, 0.f);
            if (ok) v = *reinterpret_cast<const float4*>(Gptr + (tile + 1) * BK);
        }

        // compute BK k-steps
#pragma unroll
        for (int kk = 0; kk < BK; kk++) {
            // A fragment: (a0,a0),(a1,a1) in one LDS.128
            ulonglong2 fa = *reinterpret_cast<const ulonglong2*>(&AsDup[cur][kk][tm * 4]);
            // B fragment: (b0,b1) in one LDS.64
            unsigned long long fb = *reinterpret_cast<const unsigned long long*>(&Bs[cur][kk][tn * 2]);
            ffma2(acc2[0], fa.x, fb);
            ffma2(acc2[1], fa.y, fb);
        }

        // store prefetched tile into the other buffer
        if (tile + 1 < NTILES) {
            if (isA) {
                float* ad = &AsDup[nxt][0][0];
                float vv[4] = {v.x, v.y, v.z, v.w};
#pragma unroll
                for (int i = 0; i < 4; i++)
                    *reinterpret_cast<float2*>(&ad[(lk + i) * (BM * 2) + lrow * 2]) =
                        make_float2(vv[i], vv[i]);
            } else {
                Bs[nxt][lk + 0][lrow] = v.x;
                Bs[nxt][lk + 1][lrow] = v.y;
                Bs[nxt][lk + 2][lrow] = v.z;
                Bs[nxt][lk + 3][lrow] = v.w;
            }
            __syncthreads();
        }
    }

    // epilogue: add bias, store float2 per row
    float2 b2 = *reinterpret_cast<const float2*>(&bias[bN + tn * 2]);
#pragma unroll
    for (int r = 0; r < 2; r++) {
        int gm = bM + tm * 2 + r;
        if (gm >= M) continue;
        float2 f = *reinterpret_cast<float2*>(&acc2[r]);
        *reinterpret_cast<float2*>(&out[(size_t)gm * C_ + bN + tn * 2]) =
            make_float2(f.x + b2.x, f.y + b2.y);
    }
}

// ---------------------------------------------------------------------------
// launch
// inputs: 0=query (unused), 1=reference_points, 2=image_features,
//         3=lidar2img, 4=W_out, 5=b_out; output float32 (B,Q,C)
// ---------------------------------------------------------------------------
extern "C" void kernel_launch(void* const* d_in, const int* in_sizes, int n_in,
                              void* d_out, int out_size)
{
    const float* ref_pts   = (const float*)d_in[1];
    const float* feats     = (const float*)d_in[2];
    const float* lidar2img = (const float*)d_in[3];
    const float* Wm        = (const float*)d_in[4];
    const float* bias      = (const float*)d_in[5];
    float* out = (float*)d_out;

    gather_kernel<<<BQ_, 64>>>(feats, ref_pts, lidar2img);
    dim3 gg((BQ_ + BM - 1) / BM, C_ / BN);   // 57 x 8 = 456 blocks
    gemm_kernel<<<gg, 256>>>(Wm, bias, out);
}

// round 11
// speedup vs baseline: 1.0573x; 1.0573x over previous
#include <cuda_runtime.h>
#include <cstdint>

// Problem constants (fixed shapes)
#define B_  2
#define N_  6
#define Q_  900
#define C_  256
#define H_  116
#define W_  200
#define HW_ (H_ * W_)       // 23200, divisible by 4
#define EPS_ 1e-5f
#define BQ_ (B_ * Q_)       // 1800

// Scratch (no dynamic allocation allowed)
__device__ float g_agg[BQ_ * C_];   // mean-aggregated features

// Uniform-index select from float4 (s is warp-uniform -> predicated SELs)
__device__ __forceinline__ float sel4(float4 f, int s) {
    float v = f.x;
    if (s == 1) v = f.y;
    else if (s == 2) v = f.z;
    else if (s == 3) v = f.w;
    return v;
}

// packed f32x2 fma: d = a*b + d elementwise on (lo,hi) pairs in 64-bit regs
__device__ __forceinline__ void ffma2(unsigned long long& d,
                                      unsigned long long a,
                                      unsigned long long b) {
    asm("fma.rn.f32x2 %0, %1, %2, %0;" : "+l"(d) : "l"(a), "l"(b));
}

// ---------------------------------------------------------------------------
// Fused kernel: projection (threads 0..5) + bilinear gather + camera mean
// one block per (b,q); 64 threads; 4 channels/thread (tid,+64,+128,+192)
// [identical to the R6/R9 best-known gather]
// ---------------------------------------------------------------------------
__global__ __launch_bounds__(64) void gather_kernel(
    const float* __restrict__ feats,     // (B,N,C,H,W)
    const float* __restrict__ ref_pts,   // (B,Q,3)
    const float* __restrict__ lidar2img) // (B,N,4,4)
{
    __shared__ float4 sw[N_];   // weights: (wl_top, wr_top, wl_bot, wr_bot) * valid/N
    __shared__ int4   sb[N_];   // {base_top, base_bot, s0|(s1<<8), valid}

    int bq  = blockIdx.x;       // 0..1799
    int b   = bq / Q_;
    int q   = bq % Q_;
    int tid = threadIdx.x;      // 0..63

    if (tid < N_) {
        int n = tid;
        const float* rp = ref_pts + ((size_t)b * Q_ + q) * 3;
        float px = rp[0], py = rp[1], pz = rp[2];

        const float* M = lidar2img + ((size_t)b * N_ + n) * 16;
        float xc = M[0]  * px + M[1]  * py + M[2]  * pz + M[3];
        float yc = M[4]  * px + M[5]  * py + M[6]  * pz + M[7];
        float zc = M[8]  * px + M[9]  * py + M[10] * pz + M[11];

        float denom = fabsf(zc) + EPS_;
        float x2d = xc / denom;
        float y2d = yc / denom;

        float gx = x2d / (float)(W_ - 1) * 2.0f - 1.0f;
        float gy = y2d / (float)(H_ - 1) * 2.0f - 1.0f;

        bool front  = zc > EPS_;
        bool in_img = fmaxf(fabsf(gx), fabsf(gy)) <= 1.0f;
        int  valid  = (front && in_img) ? 1 : 0;
        float vv    = valid ? (1.0f / (float)N_) : 0.0f;

        float x = ((gx + 1.0f) * (float)W_ - 1.0f) * 0.5f;
        float y = ((gy + 1.0f) * (float)H_ - 1.0f) * 0.5f;
        x = fminf(fmaxf(x, -100.0f), (float)(W_ + 100));
        y = fminf(fmaxf(y, -100.0f), (float)(H_ + 100));

        float x0f = floorf(x), y0f = floorf(y);
        float wx = x - x0f, wy = y - y0f;
        int x0 = (int)x0f, y0 = (int)y0f;
        int x1 = x0 + 1,   y1 = y0 + 1;

        float v00 = (x0 >= 0 && x0 < W_ && y0 >= 0 && y0 < H_) ? 1.0f : 0.0f;
        float v10 = (x1 >= 0 && x1 < W_ && y0 >= 0 && y0 < H_) ? 1.0f : 0.0f;
        float v01 = (x0 >= 0 && x0 < W_ && y1 >= 0 && y1 < H_) ? 1.0f : 0.0f;
        float v11 = (x1 >= 0 && x1 < W_ && y1 >= 0 && y1 < H_) ? 1.0f : 0.0f;

        float4 w;
        w.x = (1.0f - wx) * (1.0f - wy) * v00 * vv;
        w.y = wx          * (1.0f - wy) * v10 * vv;
        w.z = (1.0f - wx) * wy          * v01 * vv;
        w.w = wx          * wy          * v11 * vv;

        int cx0 = min(max(x0, 0), W_ - 1);
        int cx1 = min(max(x1, 0), W_ - 1);
        int cy0 = min(max(y0, 0), H_ - 1);
        int cy1 = min(max(y1, 0), H_ - 1);

        int i0 = cy0 * W_ + cx0;
        int i1 = cy0 * W_ + cx1;
        int j0 = cy1 * W_ + cx0;

        int base_t = i0 & ~3;
        int s0 = i0 - base_t;
        int s1 = i1 - base_t;
        int base_b = j0 - s0;

        sw[n] = w;
        sb[n] = make_int4(base_t, base_b, s0 | (s1 << 8), valid);
    }
    __syncthreads();

    float acc0 = 0.0f;   // channel tid
    float acc1 = 0.0f;   // channel tid + 64
    float acc2 = 0.0f;   // channel tid + 128
    float acc3 = 0.0f;   // channel tid + 192
#pragma unroll
    for (int n = 0; n < N_; n++) {
        int4 ib = sb[n];
        if (!ib.w) continue;            // uniform branch: camera invalid
        float4 w = sw[n];
        const float* p0 = feats + ((size_t)((b * N_ + n) * C_) + tid) * HW_;
        const float* p1 = p0 + (size_t)64  * HW_;
        const float* p2 = p0 + (size_t)128 * HW_;
        const float* p3 = p0 + (size_t)192 * HW_;

        // issue all 8 independent 16B loads before consuming
        float4 t0 = *reinterpret_cast<const float4*>(p0 + ib.x);
        float4 b0v = *reinterpret_cast<const float4*>(p0 + ib.y);
        float4 t1 = *reinterpret_cast<const float4*>(p1 + ib.x);
        float4 b1v = *reinterpret_cast<const float4*>(p1 + ib.y);
        float4 t2 = *reinterpret_cast<const float4*>(p2 + ib.x);
        float4 b2v = *reinterpret_cast<const float4*>(p2 + ib.y);
        float4 t3 = *reinterpret_cast<const float4*>(p3 + ib.x);
        float4 b3v = *reinterpret_cast<const float4*>(p3 + ib.y);

        int s0 = ib.z & 0xff;
        int s1 = ib.z >> 8;

        float vt0a = sel4(t0, s0), vb0a = sel4(b0v, s0);
        float vt0b = sel4(t1, s0), vb0b = sel4(b1v, s0);
        float vt0c = sel4(t2, s0), vb0c = sel4(b2v, s0);
        float vt0d = sel4(t3, s0), vb0d = sel4(b3v, s0);
        float vt1a, vb1a, vt1b, vb1b, vt1c, vb1c, vt1d, vb1d;
        if (s1 < 4) {                   // uniform branch (75% taken)
            vt1a = sel4(t0, s1);  vb1a = sel4(b0v, s1);
            vt1b = sel4(t1, s1);  vb1b = sel4(b1v, s1);
            vt1c = sel4(t2, s1);  vb1c = sel4(b2v, s1);
            vt1d = sel4(t3, s1);  vb1d = sel4(b3v, s1);
        } else {                        // right pixel spills into next float4
            vt1a = __ldg(p0 + ib.x + 4);  vb1a = __ldg(p0 + ib.y + 4);
            vt1b = __ldg(p1 + ib.x + 4);  vb1b = __ldg(p1 + ib.y + 4);
            vt1c = __ldg(p2 + ib.x + 4);  vb1c = __ldg(p2 + ib.y + 4);
            vt1d = __ldg(p3 + ib.x + 4);  vb1d = __ldg(p3 + ib.y + 4);
        }
        acc0 = fmaf(w.x, vt0a, acc0);
        acc0 = fmaf(w.y, vt1a, acc0);
        acc0 = fmaf(w.z, vb0a, acc0);
        acc0 = fmaf(w.w, vb1a, acc0);
        acc1 = fmaf(w.x, vt0b, acc1);
        acc1 = fmaf(w.y, vt1b, acc1);
        acc1 = fmaf(w.z, vb0b, acc1);
        acc1 = fmaf(w.w, vb1b, acc1);
        acc2 = fmaf(w.x, vt0c, acc2);
        acc2 = fmaf(w.y, vt1c, acc2);
        acc2 = fmaf(w.z, vb0c, acc2);
        acc2 = fmaf(w.w, vb1c, acc2);
        acc3 = fmaf(w.x, vt0d, acc3);
        acc3 = fmaf(w.y, vt1d, acc3);
        acc3 = fmaf(w.z, vb0d, acc3);
        acc3 = fmaf(w.w, vb1d, acc3);
    }
    float* outp = &g_agg[(size_t)bq * C_ + tid];
    outp[0]   = acc0;
    outp[64]  = acc1;
    outp[128] = acc2;
    outp[192] = acc3;
}

// ---------------------------------------------------------------------------
// Single-pass GEMM: out = agg @ W^T + bias   (M=1800, N=256, K=256)
// 32x32 tiles (grid 57x8 = 456 blocks), BK=16, double-buffered,
// 128 threads, 2x4 microtile: per k-step 2 LDS.128 -> 4 FFMA2 (ratio 2.0).
// A duplicated in smem; every thread loads one A float4 and one B float4.
// ---------------------------------------------------------------------------
#define BM 32
#define BN 32
#define BK 16
#define NTILES (C_ / BK)   // 16

__global__ __launch_bounds__(128) void gemm_kernel(const float* __restrict__ Wm,   // (256,256) row-major
                                                   const float* __restrict__ bias,
                                                   float* __restrict__ out)        // (1800,256)
{
    __shared__ float AsDup[2][BK][BM * 2];   // 8 KB: (a,a) pairs per row
    __shared__ float Bs[2][BK][BN];          // 4 KB

    const int M = BQ_;
    int t  = threadIdx.x;       // 0..127
    int tm = t >> 3;            // 0..15 -> 2 rows each
    int tn = t & 7;             // 0..7  -> 4 cols each

    int bM = blockIdx.x * BM;
    int bN = blockIdx.y * BN;

    // loaders: every thread loads one float4 of A and one float4 of B
    int lrow = t >> 2;          // 0..31
    int lk   = (t & 3) * 4;     // 0,4,8,12

    const float* Aptr = &g_agg[(size_t)(bM + lrow) * C_ + lk];
    const float* Bptr = &Wm[(size_t)(bN + lrow) * C_ + lk];
    bool arow_ok = (bM + lrow) < M;

    // accumulators: 2 rows x 2 col-pairs
    unsigned long long acc2[2][2] = {{0ull, 0ull}, {0ull, 0ull}};

    // prologue: load tile 0
    float4 av = make_float4(0.f, 0.f, 0.f, 0.f);
    if (arow_ok) av = *reinterpret_cast<const float4*>(Aptr);
    float4 bv = *reinterpret_cast<const float4*>(Bptr);
    {
        float* ad = &AsDup[0][0][0];
        float vv[4] = {av.x, av.y, av.z, av.w};
#pragma unroll
        for (int i = 0; i < 4; i++)
            *reinterpret_cast<float2*>(&ad[(lk + i) * (BM * 2) + lrow * 2]) =
                make_float2(vv[i], vv[i]);
        Bs[0][lk + 0][lrow] = bv.x;
        Bs[0][lk + 1][lrow] = bv.y;
        Bs[0][lk + 2][lrow] = bv.z;
        Bs[0][lk + 3][lrow] = bv.w;
    }
    __syncthreads();

#pragma unroll
    for (int tile = 0; tile < NTILES; tile++) {
        int cur = tile & 1;
        int nxt = cur ^ 1;

        // prefetch next tile gmem -> regs
        if (tile + 1 < NTILES) {
            av = make_float4(0.f, 0.f, 0.f, 0.f);
            if (arow_ok) av = *reinterpret_cast<const float4*>(Aptr + (tile + 1) * BK);
            bv = *reinterpret_cast<const float4*>(Bptr + (tile + 1) * BK);
        }

        // compute BK k-steps: 2 LDS.128 -> 4 FFMA2 each
#pragma unroll
        for (int kk = 0; kk < BK; kk++) {
            // A fragment: (a0,a0),(a1,a1) in one LDS.128
            ulonglong2 fa = *reinterpret_cast<const ulonglong2*>(&AsDup[cur][kk][tm * 4]);
            // B fragment: (b0,b1),(b2,b3) in one LDS.128
            ulonglong2 fb = *reinterpret_cast<const ulonglong2*>(&Bs[cur][kk][tn * 4]);
            ffma2(acc2[0][0], fa.x, fb.x);
            ffma2(acc2[0][1], fa.x, fb.y);
            ffma2(acc2[1][0], fa.y, fb.x);
            ffma2(acc2[1][1], fa.y, fb.y);
        }

        // store prefetched tile into the other buffer
        if (tile + 1 < NTILES) {
            float* ad = &AsDup[nxt][0][0];
            float vv[4] = {av.x, av.y, av.z, av.w};
#pragma unroll
            for (int i = 0; i < 4; i++)
                *reinterpret_cast<float2*>(&ad[(lk + i) * (BM * 2) + lrow * 2]) =
                    make_float2(vv[i], vv[i]);
            Bs[nxt][lk + 0][lrow] = bv.x;
            Bs[nxt][lk + 1][lrow] = bv.y;
            Bs[nxt][lk + 2][lrow] = bv.z;
            Bs[nxt][lk + 3][lrow] = bv.w;
            __syncthreads();
        }
    }

    // epilogue: add bias, store float4 per row (col-pairs contiguous)
    float4 b4 = *reinterpret_cast<const float4*>(&bias[bN + tn * 4]);
#pragma unroll
    for (int r = 0; r < 2; r++) {
        int gm = bM + tm * 2 + r;
        if (gm >= M) continue;
        float2 lo = *reinterpret_cast<float2*>(&acc2[r][0]);
        float2 hi = *reinterpret_cast<float2*>(&acc2[r][1]);
        *reinterpret_cast<float4*>(&out[(size_t)gm * C_ + bN + tn * 4]) =
            make_float4(lo.x + b4.x, lo.y + b4.y, hi.x + b4.z, hi.y + b4.w);
    }
}

// ---------------------------------------------------------------------------
// launch
// inputs: 0=query (unused), 1=reference_points, 2=image_features,
//         3=lidar2img, 4=W_out, 5=b_out; output float32 (B,Q,C)
// ---------------------------------------------------------------------------
extern "C" void kernel_launch(void* const* d_in, const int* in_sizes, int n_in,
                              void* d_out, int out_size)
{
    const float* ref_pts   = (const float*)d_in[1];
    const float* feats     = (const float*)d_in[2];
    const float* lidar2img = (const float*)d_in[3];
    const float* Wm        = (const float*)d_in[4];
    const float* bias      = (const float*)d_in[5];
    float* out = (float*)d_out;

    gather_kernel<<<BQ_, 64>>>(feats, ref_pts, lidar2img);
    dim3 gg((BQ_ + BM - 1) / BM, C_ / BN);   // 57 x 8 = 456 blocks
    gemm_kernel<<<gg, 128>>>(Wm, bias, out);
}

// round 12
// speedup vs baseline: 1.1049x; 1.0451x over previous
#include <cuda_runtime.h>
#include <cstdint>

// Problem constants (fixed shapes)
#define B_  2
#define N_  6
#define Q_  900
#define C_  256
#define H_  116
#define W_  200
#define HW_ (H_ * W_)       // 23200, divisible by 4
#define EPS_ 1e-5f
#define BQ_ (B_ * Q_)       // 1800

// Scratch (no dynamic allocation allowed)
__device__ float g_agg[BQ_ * C_];   // mean-aggregated features

// Uniform-index select from float4 (s is warp-uniform -> predicated SELs)
__device__ __forceinline__ float sel4(float4 f, int s) {
    float v = f.x;
    if (s == 1) v = f.y;
    else if (s == 2) v = f.z;
    else if (s == 3) v = f.w;
    return v;
}

// packed f32x2 fma: d = a*b + d elementwise on (lo,hi) pairs in 64-bit regs
__device__ __forceinline__ void ffma2(unsigned long long& d,
                                      unsigned long long a,
                                      unsigned long long b) {
    asm("fma.rn.f32x2 %0, %1, %2, %0;" : "+l"(d) : "l"(a), "l"(b));
}

// ---------------------------------------------------------------------------
// Fused kernel: projection (threads 0..5) + bilinear gather + camera mean
// one block per (b,q); 64 threads; 4 channels/thread (tid,+64,+128,+192)
// [identical to the R6/R9 best-known gather]
// ---------------------------------------------------------------------------
__global__ __launch_bounds__(64) void gather_kernel(
    const float* __restrict__ feats,     // (B,N,C,H,W)
    const float* __restrict__ ref_pts,   // (B,Q,3)
    const float* __restrict__ lidar2img) // (B,N,4,4)
{
    __shared__ float4 sw[N_];   // weights: (wl_top, wr_top, wl_bot, wr_bot) * valid/N
    __shared__ int4   sb[N_];   // {base_top, base_bot, s0|(s1<<8), valid}

    int bq  = blockIdx.x;       // 0..1799
    int b   = bq / Q_;
    int q   = bq % Q_;
    int tid = threadIdx.x;      // 0..63

    if (tid < N_) {
        int n = tid;
        const float* rp = ref_pts + ((size_t)b * Q_ + q) * 3;
        float px = rp[0], py = rp[1], pz = rp[2];

        const float* M = lidar2img + ((size_t)b * N_ + n) * 16;
        float xc = M[0]  * px + M[1]  * py + M[2]  * pz + M[3];
        float yc = M[4]  * px + M[5]  * py + M[6]  * pz + M[7];
        float zc = M[8]  * px + M[9]  * py + M[10] * pz + M[11];

        float denom = fabsf(zc) + EPS_;
        float x2d = xc / denom;
        float y2d = yc / denom;

        float gx = x2d / (float)(W_ - 1) * 2.0f - 1.0f;
        float gy = y2d / (float)(H_ - 1) * 2.0f - 1.0f;

        bool front  = zc > EPS_;
        bool in_img = fmaxf(fabsf(gx), fabsf(gy)) <= 1.0f;
        int  valid  = (front && in_img) ? 1 : 0;
        float vv    = valid ? (1.0f / (float)N_) : 0.0f;

        float x = ((gx + 1.0f) * (float)W_ - 1.0f) * 0.5f;
        float y = ((gy + 1.0f) * (float)H_ - 1.0f) * 0.5f;
        x = fminf(fmaxf(x, -100.0f), (float)(W_ + 100));
        y = fminf(fmaxf(y, -100.0f), (float)(H_ + 100));

        float x0f = floorf(x), y0f = floorf(y);
        float wx = x - x0f, wy = y - y0f;
        int x0 = (int)x0f, y0 = (int)y0f;
        int x1 = x0 + 1,   y1 = y0 + 1;

        float v00 = (x0 >= 0 && x0 < W_ && y0 >= 0 && y0 < H_) ? 1.0f : 0.0f;
        float v10 = (x1 >= 0 && x1 < W_ && y0 >= 0 && y0 < H_) ? 1.0f : 0.0f;
        float v01 = (x0 >= 0 && x0 < W_ && y1 >= 0 && y1 < H_) ? 1.0f : 0.0f;
        float v11 = (x1 >= 0 && x1 < W_ && y1 >= 0 && y1 < H_) ? 1.0f : 0.0f;

        float4 w;
        w.x = (1.0f - wx) * (1.0f - wy) * v00 * vv;
        w.y = wx          * (1.0f - wy) * v10 * vv;
        w.z = (1.0f - wx) * wy          * v01 * vv;
        w.w = wx          * wy          * v11 * vv;

        int cx0 = min(max(x0, 0), W_ - 1);
        int cx1 = min(max(x1, 0), W_ - 1);
        int cy0 = min(max(y0, 0), H_ - 1);
        int cy1 = min(max(y1, 0), H_ - 1);

        int i0 = cy0 * W_ + cx0;
        int i1 = cy0 * W_ + cx1;
        int j0 = cy1 * W_ + cx0;

        int base_t = i0 & ~3;
        int s0 = i0 - base_t;
        int s1 = i1 - base_t;
        int base_b = j0 - s0;

        sw[n] = w;
        sb[n] = make_int4(base_t, base_b, s0 | (s1 << 8), valid);
    }
    __syncthreads();

    float acc0 = 0.0f;   // channel tid
    float acc1 = 0.0f;   // channel tid + 64
    float acc2 = 0.0f;   // channel tid + 128
    float acc3 = 0.0f;   // channel tid + 192
#pragma unroll
    for (int n = 0; n < N_; n++) {
        int4 ib = sb[n];
        if (!ib.w) continue;            // uniform branch: camera invalid
        float4 w = sw[n];
        const float* p0 = feats + ((size_t)((b * N_ + n) * C_) + tid) * HW_;
        const float* p1 = p0 + (size_t)64  * HW_;
        const float* p2 = p0 + (size_t)128 * HW_;
        const float* p3 = p0 + (size_t)192 * HW_;

        // issue all 8 independent 16B loads before consuming
        float4 t0 = *reinterpret_cast<const float4*>(p0 + ib.x);
        float4 b0v = *reinterpret_cast<const float4*>(p0 + ib.y);
        float4 t1 = *reinterpret_cast<const float4*>(p1 + ib.x);
        float4 b1v = *reinterpret_cast<const float4*>(p1 + ib.y);
        float4 t2 = *reinterpret_cast<const float4*>(p2 + ib.x);
        float4 b2v = *reinterpret_cast<const float4*>(p2 + ib.y);
        float4 t3 = *reinterpret_cast<const float4*>(p3 + ib.x);
        float4 b3v = *reinterpret_cast<const float4*>(p3 + ib.y);

        int s0 = ib.z & 0xff;
        int s1 = ib.z >> 8;

        float vt0a = sel4(t0, s0), vb0a = sel4(b0v, s0);
        float vt0b = sel4(t1, s0), vb0b = sel4(b1v, s0);
        float vt0c = sel4(t2, s0), vb0c = sel4(b2v, s0);
        float vt0d = sel4(t3, s0), vb0d = sel4(b3v, s0);
        float vt1a, vb1a, vt1b, vb1b, vt1c, vb1c, vt1d, vb1d;
        if (s1 < 4) {                   // uniform branch (75% taken)
            vt1a = sel4(t0, s1);  vb1a = sel4(b0v, s1);
            vt1b = sel4(t1, s1);  vb1b = sel4(b1v, s1);
            vt1c = sel4(t2, s1);  vb1c = sel4(b2v, s1);
            vt1d = sel4(t3, s1);  vb1d = sel4(b3v, s1);
        } else {                        // right pixel spills into next float4
            vt1a = __ldg(p0 + ib.x + 4);  vb1a = __ldg(p0 + ib.y + 4);
            vt1b = __ldg(p1 + ib.x + 4);  vb1b = __ldg(p1 + ib.y + 4);
            vt1c = __ldg(p2 + ib.x + 4);  vb1c = __ldg(p2 + ib.y + 4);
            vt1d = __ldg(p3 + ib.x + 4);  vb1d = __ldg(p3 + ib.y + 4);
        }
        acc0 = fmaf(w.x, vt0a, acc0);
        acc0 = fmaf(w.y, vt1a, acc0);
        acc0 = fmaf(w.z, vb0a, acc0);
        acc0 = fmaf(w.w, vb1a, acc0);
        acc1 = fmaf(w.x, vt0b, acc1);
        acc1 = fmaf(w.y, vt1b, acc1);
        acc1 = fmaf(w.z, vb0b, acc1);
        acc1 = fmaf(w.w, vb1b, acc1);
        acc2 = fmaf(w.x, vt0c, acc2);
        acc2 = fmaf(w.y, vt1c, acc2);
        acc2 = fmaf(w.z, vb0c, acc2);
        acc2 = fmaf(w.w, vb1c, acc2);
        acc3 = fmaf(w.x, vt0d, acc3);
        acc3 = fmaf(w.y, vt1d, acc3);
        acc3 = fmaf(w.z, vb0d, acc3);
        acc3 = fmaf(w.w, vb1d, acc3);
    }
    float* outp = &g_agg[(size_t)bq * C_ + tid];
    outp[0]   = acc0;
    outp[64]  = acc1;
    outp[128] = acc2;
    outp[192] = acc3;
}

// ---------------------------------------------------------------------------
// Single-pass GEMM with in-block split-K:
// out = agg @ W^T + bias   (M=1800, N=256, K=256)
// 32x32 tiles (grid 57x8 = 456 blocks), 256 threads = 2 k-groups x 128.
// Each group: 2x4 microtile over K/2=128 (8 double-buffered BK=16 tiles),
// per k-step 2 LDS.128 -> 4 FFMA2. Partials merged via smem, bias epilogue.
// ---------------------------------------------------------------------------
#define BM 32
#define BN 32
#define BK 16
#define KHALF (C_ / 2)     // 128
#define NT (KHALF / BK)    // 8 tiles per k-group

__global__ __launch_bounds__(256) void gemm_kernel(const float* __restrict__ Wm,   // (256,256) row-major
                                                   const float* __restrict__ bias,
                                                   float* __restrict__ out)        // (1800,256)
{
    __shared__ float AsDup[2][2][BK][BM * 2];   // [kg][buf] 16 KB
    __shared__ float Bs[2][2][BK][BN];          // [kg][buf]  8 KB
    __shared__ float Red[128][8];               // 4 KB partial exchange

    const int M = BQ_;
    int t  = threadIdx.x;       // 0..255
    int kg = t >> 7;            // k-group 0/1
    int u  = t & 127;
    int tm = u >> 3;            // 0..15 -> 2 rows each
    int tn = u & 7;             // 0..7  -> 4 cols each

    int bM = blockIdx.x * BM;
    int bN = blockIdx.y * BN;

    // loaders: each group's 128 threads load their own A/B float4 per tile
    int lrow = u >> 2;          // 0..31
    int lk   = (u & 3) * 4;     // 0,4,8,12
    int koff = kg * KHALF;

    const float* Aptr = &g_agg[(size_t)(bM + lrow) * C_ + koff + lk];
    const float* Bptr = &Wm[(size_t)(bN + lrow) * C_ + koff + lk];
    bool arow_ok = (bM + lrow) < M;

    // accumulators: 2 rows x 2 col-pairs
    unsigned long long acc2[2][2] = {{0ull, 0ull}, {0ull, 0ull}};

    // prologue: load tile 0 of this k-group
    float4 av = make_float4(0.f, 0.f, 0.f, 0.f);
    if (arow_ok) av = *reinterpret_cast<const float4*>(Aptr);
    float4 bv = *reinterpret_cast<const float4*>(Bptr);
    {
        float* ad = &AsDup[kg][0][0][0];
        float vv[4] = {av.x, av.y, av.z, av.w};
#pragma unroll
        for (int i = 0; i < 4; i++)
            *reinterpret_cast<float2*>(&ad[(lk + i) * (BM * 2) + lrow * 2]) =
                make_float2(vv[i], vv[i]);
        Bs[kg][0][lk + 0][lrow] = bv.x;
        Bs[kg][0][lk + 1][lrow] = bv.y;
        Bs[kg][0][lk + 2][lrow] = bv.z;
        Bs[kg][0][lk + 3][lrow] = bv.w;
    }
    __syncthreads();

#pragma unroll
    for (int tile = 0; tile < NT; tile++) {
        int cur = tile & 1;
        int nxt = cur ^ 1;

        // prefetch next tile gmem -> regs
        if (tile + 1 < NT) {
            av = make_float4(0.f, 0.f, 0.f, 0.f);
            if (arow_ok) av = *reinterpret_cast<const float4*>(Aptr + (tile + 1) * BK);
            bv = *reinterpret_cast<const float4*>(Bptr + (tile + 1) * BK);
        }

        // compute BK k-steps: 2 LDS.128 -> 4 FFMA2 each
#pragma unroll
        for (int kk = 0; kk < BK; kk++) {
            ulonglong2 fa = *reinterpret_cast<const ulonglong2*>(&AsDup[kg][cur][kk][tm * 4]);
            ulonglong2 fb = *reinterpret_cast<const ulonglong2*>(&Bs[kg][cur][kk][tn * 4]);
            ffma2(acc2[0][0], fa.x, fb.x);
            ffma2(acc2[0][1], fa.x, fb.y);
            ffma2(acc2[1][0], fa.y, fb.x);
            ffma2(acc2[1][1], fa.y, fb.y);
        }

        // store prefetched tile into the other buffer
        if (tile + 1 < NT) {
            float* ad = &AsDup[kg][nxt][0][0];
            float vv[4] = {av.x, av.y, av.z, av.w};
#pragma unroll
            for (int i = 0; i < 4; i++)
                *reinterpret_cast<float2*>(&ad[(lk + i) * (BM * 2) + lrow * 2]) =
                    make_float2(vv[i], vv[i]);
            Bs[kg][nxt][lk + 0][lrow] = bv.x;
            Bs[kg][nxt][lk + 1][lrow] = bv.y;
            Bs[kg][nxt][lk + 2][lrow] = bv.z;
            Bs[kg][nxt][lk + 3][lrow] = bv.w;
            __syncthreads();
        }
    }

    // merge k-groups: group 1 publishes partials, group 0 reduces + stores
    __syncthreads();
    if (kg == 1) {
#pragma unroll
        for (int r = 0; r < 2; r++) {
            float2 lo = *reinterpret_cast<float2*>(&acc2[r][0]);
            float2 hi = *reinterpret_cast<float2*>(&acc2[r][1]);
            Red[u][r * 4 + 0] = lo.x;
            Red[u][r * 4 + 1] = lo.y;
            Red[u][r * 4 + 2] = hi.x;
            Red[u][r * 4 + 3] = hi.y;
        }
    }
    __syncthreads();
    if (kg == 0) {
        float4 b4 = *reinterpret_cast<const float4*>(&bias[bN + tn * 4]);
#pragma unroll
        for (int r = 0; r < 2; r++) {
            int gm = bM + tm * 2 + r;
            if (gm >= M) continue;
            float2 lo = *reinterpret_cast<float2*>(&acc2[r][0]);
            float2 hi = *reinterpret_cast<float2*>(&acc2[r][1]);
            float o0 = lo.x + Red[u][r * 4 + 0] + b4.x;
            float o1 = lo.y + Red[u][r * 4 + 1] + b4.y;
            float o2 = hi.x + Red[u][r * 4 + 2] + b4.z;
            float o3 = hi.y + Red[u][r * 4 + 3] + b4.w;
            *reinterpret_cast<float4*>(&out[(size_t)gm * C_ + bN + tn * 4]) =
                make_float4(o0, o1, o2, o3);
        }
    }
}

// ---------------------------------------------------------------------------
// launch
// inputs: 0=query (unused), 1=reference_points, 2=image_features,
//         3=lidar2img, 4=W_out, 5=b_out; output float32 (B,Q,C)
// ---------------------------------------------------------------------------
extern "C" void kernel_launch(void* const* d_in, const int* in_sizes, int n_in,
                              void* d_out, int out_size)
{
    const float* ref_pts   = (const float*)d_in[1];
    const float* feats     = (const float*)d_in[2];
    const float* lidar2img = (const float*)d_in[3];
    const float* Wm        = (const float*)d_in[4];
    const float* bias      = (const float*)d_in[5];
    float* out = (float*)d_out;

    gather_kernel<<<BQ_, 64>>>(feats, ref_pts, lidar2img);
    dim3 gg((BQ_ + BM - 1) / BM, C_ / BN);   // 57 x 8 = 456 blocks
    gemm_kernel<<<gg, 256>>>(Wm, bias, out);
}

// round 13
// speedup vs baseline: 1.2019x; 1.0878x over previous
#include <cuda_runtime.h>
#include <cstdint>

// Problem constants (fixed shapes)
#define B_  2
#define N_  6
#define Q_  900
#define C_  256
#define H_  116
#define W_  200
#define HW_ (H_ * W_)       // 23200, divisible by 4
#define EPS_ 1e-5f
#define BQ_ (B_ * Q_)       // 1800

// Scratch (no dynamic allocation allowed)
__device__ float g_agg[BQ_ * C_];   // mean-aggregated features

// Uniform-index select from float4 (s is warp-uniform -> predicated SELs)
__device__ __forceinline__ float sel4(float4 f, int s) {
    float v = f.x;
    if (s == 1) v = f.y;
    else if (s == 2) v = f.z;
    else if (s == 3) v = f.w;
    return v;
}

// packed f32x2 fma: d = a*b + d elementwise on (lo,hi) pairs in 64-bit regs
__device__ __forceinline__ void ffma2(unsigned long long& d,
                                      unsigned long long a,
                                      unsigned long long b) {
    asm("fma.rn.f32x2 %0, %1, %2, %0;" : "+l"(d) : "l"(a), "l"(b));
}

// swap the two 32-bit halves of a 64-bit pair
__device__ __forceinline__ unsigned long long swap2(unsigned long long p) {
    return (p >> 32) | (p << 32);
}

// ---------------------------------------------------------------------------
// Fused kernel: projection (threads 0..5) + bilinear gather + camera mean
// one block per (b,q); 64 threads; 4 channels/thread (tid,+64,+128,+192)
// [identical to the R6/R9 best-known gather]
// ---------------------------------------------------------------------------
__global__ __launch_bounds__(64) void gather_kernel(
    const float* __restrict__ feats,     // (B,N,C,H,W)
    const float* __restrict__ ref_pts,   // (B,Q,3)
    const float* __restrict__ lidar2img) // (B,N,4,4)
{
    __shared__ float4 sw[N_];
    __shared__ int4   sb[N_];

    int bq  = blockIdx.x;
    int b   = bq / Q_;
    int q   = bq % Q_;
    int tid = threadIdx.x;

    if (tid < N_) {
        int n = tid;
        const float* rp = ref_pts + ((size_t)b * Q_ + q) * 3;
        float px = rp[0], py = rp[1], pz = rp[2];

        const float* M = lidar2img + ((size_t)b * N_ + n) * 16;
        float xc = M[0]  * px + M[1]  * py + M[2]  * pz + M[3];
        float yc = M[4]  * px + M[5]  * py + M[6]  * pz + M[7];
        float zc = M[8]  * px + M[9]  * py + M[10] * pz + M[11];

        float denom = fabsf(zc) + EPS_;
        float x2d = xc / denom;
        float y2d = yc / denom;

        float gx = x2d / (float)(W_ - 1) * 2.0f - 1.0f;
        float gy = y2d / (float)(H_ - 1) * 2.0f - 1.0f;

        bool front  = zc > EPS_;
        bool in_img = fmaxf(fabsf(gx), fabsf(gy)) <= 1.0f;
        int  valid  = (front && in_img) ? 1 : 0;
        float vv    = valid ? (1.0f / (float)N_) : 0.0f;

        float x = ((gx + 1.0f) * (float)W_ - 1.0f) * 0.5f;
        float y = ((gy + 1.0f) * (float)H_ - 1.0f) * 0.5f;
        x = fminf(fmaxf(x, -100.0f), (float)(W_ + 100));
        y = fminf(fmaxf(y, -100.0f), (float)(H_ + 100));

        float x0f = floorf(x), y0f = floorf(y);
        float wx = x - x0f, wy = y - y0f;
        int x0 = (int)x0f, y0 = (int)y0f;
        int x1 = x0 + 1,   y1 = y0 + 1;

        float v00 = (x0 >= 0 && x0 < W_ && y0 >= 0 && y0 < H_) ? 1.0f : 0.0f;
        float v10 = (x1 >= 0 && x1 < W_ && y0 >= 0 && y0 < H_) ? 1.0f : 0.0f;
        float v01 = (x0 >= 0 && x0 < W_ && y1 >= 0 && y1 < H_) ? 1.0f : 0.0f;
        float v11 = (x1 >= 0 && x1 < W_ && y1 >= 0 && y1 < H_) ? 1.0f : 0.0f;

        float4 w;
        w.x = (1.0f - wx) * (1.0f - wy) * v00 * vv;
        w.y = wx          * (1.0f - wy) * v10 * vv;
        w.z = (1.0f - wx) * wy          * v01 * vv;
        w.w = wx          * wy          * v11 * vv;

        int cx0 = min(max(x0, 0), W_ - 1);
        int cx1 = min(max(x1, 0), W_ - 1);
        int cy0 = min(max(y0, 0), H_ - 1);
        int cy1 = min(max(y1, 0), H_ - 1);

        int i0 = cy0 * W_ + cx0;
        int i1 = cy0 * W_ + cx1;
        int j0 = cy1 * W_ + cx0;

        int base_t = i0 & ~3;
        int s0 = i0 - base_t;
        int s1 = i1 - base_t;
        int base_b = j0 - s0;

        sw[n] = w;
        sb[n] = make_int4(base_t, base_b, s0 | (s1 << 8), valid);
    }
    __syncthreads();

    float acc0 = 0.0f, acc1 = 0.0f, acc2 = 0.0f, acc3 = 0.0f;
#pragma unroll
    for (int n = 0; n < N_; n++) {
        int4 ib = sb[n];
        if (!ib.w) continue;
        float4 w = sw[n];
        const float* p0 = feats + ((size_t)((b * N_ + n) * C_) + tid) * HW_;
        const float* p1 = p0 + (size_t)64  * HW_;
        const float* p2 = p0 + (size_t)128 * HW_;
        const float* p3 = p0 + (size_t)192 * HW_;

        float4 t0 = *reinterpret_cast<const float4*>(p0 + ib.x);
        float4 b0v = *reinterpret_cast<const float4*>(p0 + ib.y);
        float4 t1 = *reinterpret_cast<const float4*>(p1 + ib.x);
        float4 b1v = *reinterpret_cast<const float4*>(p1 + ib.y);
        float4 t2 = *reinterpret_cast<const float4*>(p2 + ib.x);
        float4 b2v = *reinterpret_cast<const float4*>(p2 + ib.y);
        float4 t3 = *reinterpret_cast<const float4*>(p3 + ib.x);
        float4 b3v = *reinterpret_cast<const float4*>(p3 + ib.y);

        int s0 = ib.z & 0xff;
        int s1 = ib.z >> 8;

        float vt0a = sel4(t0, s0), vb0a = sel4(b0v, s0);
        float vt0b = sel4(t1, s0), vb0b = sel4(b1v, s0);
        float vt0c = sel4(t2, s0), vb0c = sel4(b2v, s0);
        float vt0d = sel4(t3, s0), vb0d = sel4(b3v, s0);
        float vt1a, vb1a, vt1b, vb1b, vt1c, vb1c, vt1d, vb1d;
        if (s1 < 4) {
            vt1a = sel4(t0, s1);  vb1a = sel4(b0v, s1);
            vt1b = sel4(t1, s1);  vb1b = sel4(b1v, s1);
            vt1c = sel4(t2, s1);  vb1c = sel4(b2v, s1);
            vt1d = sel4(t3, s1);  vb1d = sel4(b3v, s1);
        } else {
            vt1a = __ldg(p0 + ib.x + 4);  vb1a = __ldg(p0 + ib.y + 4);
            vt1b = __ldg(p1 + ib.x + 4);  vb1b = __ldg(p1 + ib.y + 4);
            vt1c = __ldg(p2 + ib.x + 4);  vb1c = __ldg(p2 + ib.y + 4);
            vt1d = __ldg(p3 + ib.x + 4);  vb1d = __ldg(p3 + ib.y + 4);
        }
        acc0 = fmaf(w.x, vt0a, acc0);
        acc0 = fmaf(w.y, vt1a, acc0);
        acc0 = fmaf(w.z, vb0a, acc0);
        acc0 = fmaf(w.w, vb1a, acc0);
        acc1 = fmaf(w.x, vt0b, acc1);
        acc1 = fmaf(w.y, vt1b, acc1);
        acc1 = fmaf(w.z, vb0b, acc1);
        acc1 = fmaf(w.w, vb1b, acc1);
        acc2 = fmaf(w.x, vt0c, acc2);
        acc2 = fmaf(w.y, vt1c, acc2);
        acc2 = fmaf(w.z, vb0c, acc2);
        acc2 = fmaf(w.w, vb1c, acc2);
        acc3 = fmaf(w.x, vt0d, acc3);
        acc3 = fmaf(w.y, vt1d, acc3);
        acc3 = fmaf(w.z, vb0d, acc3);
        acc3 = fmaf(w.w, vb1d, acc3);
    }
    float* outp = &g_agg[(size_t)bq * C_ + tid];
    outp[0]   = acc0;
    outp[64]  = acc1;
    outp[128] = acc2;
    outp[192] = acc3;
}

// ---------------------------------------------------------------------------
// GEMM: out = agg @ W^T + bias  (M=1800, N=256, K=256)
// 32x32 tiles, grid 57x8 = 456 blocks, 256 threads = 4 k-groups x 64.
// Each group: K-chunk 64, BK=16 double-buffered, 4x4 microtile with
// NATURAL-PAIR fragments (no smem duplication): per k-step 2 LDS.128 ->
// 8 FFMA2 (diag + swapped-cross pairs) = 16 MACs / 8 floats (ratio 2.0).
// Partials reduced through smem, bias in epilogue. Deterministic order.
// ---------------------------------------------------------------------------
#define BM 32
#define BN 32
#define BK 16
#define KG 4
#define KCH (C_ / KG)      // 64
#define NTg (KCH / BK)     // 4 tiles per group

__global__ __launch_bounds__(256) void gemm_kernel(const float* __restrict__ Wm,   // (256,256) row-major
                                                   const float* __restrict__ bias,
                                                   float* __restrict__ out)        // (1800,256)
{
    __shared__ float As[KG][2][BK][BM];   // 16 KB  As[g][buf][k][row]
    __shared__ float Bs[KG][2][BK][BN];   // 16 KB  Bs[g][buf][k][col]
    __shared__ float Red[KG][BM * BN];    // 16 KB  partials (plain layout)

    const int M = BQ_;
    int t  = threadIdx.x;       // 0..255
    int kg = t >> 6;            // k-group 0..3
    int u  = t & 63;            // lane in group
    int tm = u >> 3;            // 0..7 -> rows tm*4..+3
    int tn = u & 7;             // 0..7 -> cols tn*4..+3

    int bM = blockIdx.x * BM;
    int bN = blockIdx.y * BN;
    int koff = kg * KCH;

    // loader mapping: 128 float4 per tile (A) -> 2 per thread; same for B.
    int r1 = u >> 2;            // 0..15 ; second row = r1 + 16
    int k4 = (u & 3) * 4;       // 0,4,8,12

    const float* Ap0 = &g_agg[(size_t)(bM + r1) * C_ + koff + k4];
    const float* Ap1 = Ap0 + (size_t)16 * C_;
    const float* Bp0 = &Wm[(size_t)(bN + r1) * C_ + koff + k4];
    const float* Bp1 = Bp0 + (size_t)16 * C_;
    bool ok0 = (bM + r1) < M;
    bool ok1 = (bM + r1 + 16) < M;

    // accumulators in diagonal-pair form:
    // accd[rp][jp] = (C[r0][c0], C[r1][c1]), accx[rp][jp] = (C[r0][c1], C[r1][c0])
    unsigned long long accd[2][2] = {{0ull, 0ull}, {0ull, 0ull}};
    unsigned long long accx[2][2] = {{0ull, 0ull}, {0ull, 0ull}};

    // prologue: load tile 0
    float4 a0 = make_float4(0.f, 0.f, 0.f, 0.f), a1 = a0;
    if (ok0) a0 = *reinterpret_cast<const float4*>(Ap0);
    if (ok1) a1 = *reinterpret_cast<const float4*>(Ap1);
    float4 b0 = *reinterpret_cast<const float4*>(Bp0);
    float4 b1 = *reinterpret_cast<const float4*>(Bp1);
    {
        float va0[4] = {a0.x, a0.y, a0.z, a0.w};
        float va1[4] = {a1.x, a1.y, a1.z, a1.w};
        float vb0[4] = {b0.x, b0.y, b0.z, b0.w};
        float vb1[4] = {b1.x, b1.y, b1.z, b1.w};
#pragma unroll
        for (int i = 0; i < 4; i++) {
            As[kg][0][k4 + i][r1]      = va0[i];
            As[kg][0][k4 + i][r1 + 16] = va1[i];
            Bs[kg][0][k4 + i][r1]      = vb0[i];
            Bs[kg][0][k4 + i][r1 + 16] = vb1[i];
        }
    }
    asm volatile("bar.sync %0, 64;" :: "r"(kg + 1) : "memory");

#pragma unroll
    for (int tile = 0; tile < NTg; tile++) {
        int cur = tile & 1;
        int nxt = cur ^ 1;

        // prefetch next tile gmem -> regs
        if (tile + 1 < NTg) {
            a0 = make_float4(0.f, 0.f, 0.f, 0.f);
            a1 = a0;
            if (ok0) a0 = *reinterpret_cast<const float4*>(Ap0 + (tile + 1) * BK);
            if (ok1) a1 = *reinterpret_cast<const float4*>(Ap1 + (tile + 1) * BK);
            b0 = *reinterpret_cast<const float4*>(Bp0 + (tile + 1) * BK);
            b1 = *reinterpret_cast<const float4*>(Bp1 + (tile + 1) * BK);
        }

        // compute BK k-steps: 2 LDS.128 -> 8 FFMA2 each
#pragma unroll
        for (int kk = 0; kk < BK; kk++) {
            ulonglong2 fa = *reinterpret_cast<const ulonglong2*>(&As[kg][cur][kk][tm * 4]);
            ulonglong2 fb = *reinterpret_cast<const ulonglong2*>(&Bs[kg][cur][kk][tn * 4]);
            unsigned long long bs0 = swap2(fb.x);
            unsigned long long bs1 = swap2(fb.y);
            ffma2(accd[0][0], fa.x, fb.x);
            ffma2(accx[0][0], fa.x, bs0);
            ffma2(accd[0][1], fa.x, fb.y);
            ffma2(accx[0][1], fa.x, bs1);
            ffma2(accd[1][0], fa.y, fb.x);
            ffma2(accx[1][0], fa.y, bs0);
            ffma2(accd[1][1], fa.y, fb.y);
            ffma2(accx[1][1], fa.y, bs1);
        }

        // store prefetched tile into the other buffer
        if (tile + 1 < NTg) {
            float va0[4] = {a0.x, a0.y, a0.z, a0.w};
            float va1[4] = {a1.x, a1.y, a1.z, a1.w};
            float vb0[4] = {b0.x, b0.y, b0.z, b0.w};
            float vb1[4] = {b1.x, b1.y, b1.z, b1.w};
#pragma unroll
            for (int i = 0; i < 4; i++) {
                As[kg][nxt][k4 + i][r1]      = va0[i];
                As[kg][nxt][k4 + i][r1 + 16] = va1[i];
                Bs[kg][nxt][k4 + i][r1]      = vb0[i];
                Bs[kg][nxt][k4 + i][r1 + 16] = vb1[i];
            }
            asm volatile("bar.sync %0, 64;" :: "r"(kg + 1) : "memory");
        }
    }

    // unpack diagonal pairs into plain partial layout in smem
#pragma unroll
    for (int rp = 0; rp < 2; rp++) {
#pragma unroll
        for (int jp = 0; jp < 2; jp++) {
            float2 d = *reinterpret_cast<float2*>(&accd[rp][jp]);
            float2 x = *reinterpret_cast<float2*>(&accx[rp][jp]);
            int r0 = tm * 4 + rp * 2;
            int c0 = tn * 4 + jp * 2;
            // C[r0][c0]=d.x, C[r0][c1]=x.x, C[r1][c0]=x.y, C[r1][c1]=d.y
            *reinterpret_cast<float2*>(&Red[kg][r0 * BN + c0])       = make_float2(d.x, x.x);
            *reinterpret_cast<float2*>(&Red[kg][(r0 + 1) * BN + c0]) = make_float2(x.y, d.y);
        }
    }
    __syncthreads();

    // reduce 4 partials + bias, store (256 threads x 4 floats = 1024 outputs)
    {
        int e   = t * 4;            // 0..1020
        int row = t >> 3;           // e / 32
        int col = (t & 7) * 4;      // e % 32
        float4 s  = *reinterpret_cast<const float4*>(&Red[0][e]);
        float4 p1v = *reinterpret_cast<const float4*>(&Red[1][e]);
        float4 p2v = *reinterpret_cast<const float4*>(&Red[2][e]);
        float4 p3v = *reinterpret_cast<const float4*>(&Red[3][e]);
        s.x += p1v.x; s.y += p1v.y; s.z += p1v.z; s.w += p1v.w;
        s.x += p2v.x; s.y += p2v.y; s.z += p2v.z; s.w += p2v.w;
        s.x += p3v.x; s.y += p3v.y; s.z += p3v.z; s.w += p3v.w;
        float4 bb = *reinterpret_cast<const float4*>(&bias[bN + col]);
        s.x += bb.x; s.y += bb.y; s.z += bb.z; s.w += bb.w;
        int gm = bM + row;
        if (gm < M)
            *reinterpret_cast<float4*>(&out[(size_t)gm * C_ + bN + col]) = s;
    }
}

// ---------------------------------------------------------------------------
// launch
// inputs: 0=query (unused), 1=reference_points, 2=image_features,
//         3=lidar2img, 4=W_out, 5=b_out; output float32 (B,Q,C)
// ---------------------------------------------------------------------------
extern "C" void kernel_launch(void* const* d_in, const int* in_sizes, int n_in,
                              void* d_out, int out_size)
{
    const float* ref_pts   = (const float*)d_in[1];
    const float* feats     = (const float*)d_in[2];
    const float* lidar2img = (const float*)d_in[3];
    const float* Wm        = (const float*)d_in[4];
    const float* bias      = (const float*)d_in[5];
    float* out = (float*)d_out;

    gather_kernel<<<BQ_, 64>>>(feats, ref_pts, lidar2img);
    dim3 gg((BQ_ + BM - 1) / BM, C_ / BN);   // 57 x 8 = 456 blocks
    gemm_kernel<<<gg, 256>>>(Wm, bias, out);
}

// round 14
// speedup vs baseline: 1.2090x; 1.0059x over previous
#include <cuda_runtime.h>
#include <cstdint>

// Problem constants (fixed shapes)
#define B_  2
#define N_  6
#define Q_  900
#define C_  256
#define H_  116
#define W_  200
#define HW_ (H_ * W_)       // 23200, divisible by 4
#define EPS_ 1e-5f
#define BQ_ (B_ * Q_)       // 1800

// Scratch (no dynamic allocation allowed)
__device__ float g_agg[BQ_ * C_];   // mean-aggregated features

// Uniform-index select from float4 (s is warp-uniform -> predicated SELs)
__device__ __forceinline__ float sel4(float4 f, int s) {
    float v = f.x;
    if (s == 1) v = f.y;
    else if (s == 2) v = f.z;
    else if (s == 3) v = f.w;
    return v;
}

// packed f32x2 fma: d = a*b + d elementwise on (lo,hi) pairs in 64-bit regs
__device__ __forceinline__ void ffma2(unsigned long long& d,
                                      unsigned long long a,
                                      unsigned long long b) {
    asm("fma.rn.f32x2 %0, %1, %2, %0;" : "+l"(d) : "l"(a), "l"(b));
}

// swap the two 32-bit halves of a 64-bit pair
__device__ __forceinline__ unsigned long long swap2(unsigned long long p) {
    return (p >> 32) | (p << 32);
}

// ---------------------------------------------------------------------------
// Fused kernel: projection (threads 0..5) + bilinear gather + camera mean
// one block per (b,q); 64 threads; 4 channels/thread (tid,+64,+128,+192)
// [identical to the R6/R9/R13 best-known gather]
// ---------------------------------------------------------------------------
__global__ __launch_bounds__(64) void gather_kernel(
    const float* __restrict__ feats,     // (B,N,C,H,W)
    const float* __restrict__ ref_pts,   // (B,Q,3)
    const float* __restrict__ lidar2img) // (B,N,4,4)
{
    __shared__ float4 sw[N_];
    __shared__ int4   sb[N_];

    int bq  = blockIdx.x;
    int b   = bq / Q_;
    int q   = bq % Q_;
    int tid = threadIdx.x;

    if (tid < N_) {
        int n = tid;
        const float* rp = ref_pts + ((size_t)b * Q_ + q) * 3;
        float px = rp[0], py = rp[1], pz = rp[2];

        const float* M = lidar2img + ((size_t)b * N_ + n) * 16;
        float xc = M[0]  * px + M[1]  * py + M[2]  * pz + M[3];
        float yc = M[4]  * px + M[5]  * py + M[6]  * pz + M[7];
        float zc = M[8]  * px + M[9]  * py + M[10] * pz + M[11];

        float denom = fabsf(zc) + EPS_;
        float x2d = xc / denom;
        float y2d = yc / denom;

        float gx = x2d / (float)(W_ - 1) * 2.0f - 1.0f;
        float gy = y2d / (float)(H_ - 1) * 2.0f - 1.0f;

        bool front  = zc > EPS_;
        bool in_img = fmaxf(fabsf(gx), fabsf(gy)) <= 1.0f;
        int  valid  = (front && in_img) ? 1 : 0;
        float vv    = valid ? (1.0f / (float)N_) : 0.0f;

        float x = ((gx + 1.0f) * (float)W_ - 1.0f) * 0.5f;
        float y = ((gy + 1.0f) * (float)H_ - 1.0f) * 0.5f;
        x = fminf(fmaxf(x, -100.0f), (float)(W_ + 100));
        y = fminf(fmaxf(y, -100.0f), (float)(H_ + 100));

        float x0f = floorf(x), y0f = floorf(y);
        float wx = x - x0f, wy = y - y0f;
        int x0 = (int)x0f, y0 = (int)y0f;
        int x1 = x0 + 1,   y1 = y0 + 1;

        float v00 = (x0 >= 0 && x0 < W_ && y0 >= 0 && y0 < H_) ? 1.0f : 0.0f;
        float v10 = (x1 >= 0 && x1 < W_ && y0 >= 0 && y0 < H_) ? 1.0f : 0.0f;
        float v01 = (x0 >= 0 && x0 < W_ && y1 >= 0 && y1 < H_) ? 1.0f : 0.0f;
        float v11 = (x1 >= 0 && x1 < W_ && y1 >= 0 && y1 < H_) ? 1.0f : 0.0f;

        float4 w;
        w.x = (1.0f - wx) * (1.0f - wy) * v00 * vv;
        w.y = wx          * (1.0f - wy) * v10 * vv;
        w.z = (1.0f - wx) * wy          * v01 * vv;
        w.w = wx          * wy          * v11 * vv;

        int cx0 = min(max(x0, 0), W_ - 1);
        int cx1 = min(max(x1, 0), W_ - 1);
        int cy0 = min(max(y0, 0), H_ - 1);
        int cy1 = min(max(y1, 0), H_ - 1);

        int i0 = cy0 * W_ + cx0;
        int i1 = cy0 * W_ + cx1;
        int j0 = cy1 * W_ + cx0;

        int base_t = i0 & ~3;
        int s0 = i0 - base_t;
        int s1 = i1 - base_t;
        int base_b = j0 - s0;

        sw[n] = w;
        sb[n] = make_int4(base_t, base_b, s0 | (s1 << 8), valid);
    }
    __syncthreads();

    float acc0 = 0.0f, acc1 = 0.0f, acc2 = 0.0f, acc3 = 0.0f;
#pragma unroll
    for (int n = 0; n < N_; n++) {
        int4 ib = sb[n];
        if (!ib.w) continue;
        float4 w = sw[n];
        const float* p0 = feats + ((size_t)((b * N_ + n) * C_) + tid) * HW_;
        const float* p1 = p0 + (size_t)64  * HW_;
        const float* p2 = p0 + (size_t)128 * HW_;
        const float* p3 = p0 + (size_t)192 * HW_;

        float4 t0 = *reinterpret_cast<const float4*>(p0 + ib.x);
        float4 b0v = *reinterpret_cast<const float4*>(p0 + ib.y);
        float4 t1 = *reinterpret_cast<const float4*>(p1 + ib.x);
        float4 b1v = *reinterpret_cast<const float4*>(p1 + ib.y);
        float4 t2 = *reinterpret_cast<const float4*>(p2 + ib.x);
        float4 b2v = *reinterpret_cast<const float4*>(p2 + ib.y);
        float4 t3 = *reinterpret_cast<const float4*>(p3 + ib.x);
        float4 b3v = *reinterpret_cast<const float4*>(p3 + ib.y);

        int s0 = ib.z & 0xff;
        int s1 = ib.z >> 8;

        float vt0a = sel4(t0, s0), vb0a = sel4(b0v, s0);
        float vt0b = sel4(t1, s0), vb0b = sel4(b1v, s0);
        float vt0c = sel4(t2, s0), vb0c = sel4(b2v, s0);
        float vt0d = sel4(t3, s0), vb0d = sel4(b3v, s0);
        float vt1a, vb1a, vt1b, vb1b, vt1c, vb1c, vt1d, vb1d;
        if (s1 < 4) {
            vt1a = sel4(t0, s1);  vb1a = sel4(b0v, s1);
            vt1b = sel4(t1, s1);  vb1b = sel4(b1v, s1);
            vt1c = sel4(t2, s1);  vb1c = sel4(b2v, s1);
            vt1d = sel4(t3, s1);  vb1d = sel4(b3v, s1);
        } else {
            vt1a = __ldg(p0 + ib.x + 4);  vb1a = __ldg(p0 + ib.y + 4);
            vt1b = __ldg(p1 + ib.x + 4);  vb1b = __ldg(p1 + ib.y + 4);
            vt1c = __ldg(p2 + ib.x + 4);  vb1c = __ldg(p2 + ib.y + 4);
            vt1d = __ldg(p3 + ib.x + 4);  vb1d = __ldg(p3 + ib.y + 4);
        }
        acc0 = fmaf(w.x, vt0a, acc0);
        acc0 = fmaf(w.y, vt1a, acc0);
        acc0 = fmaf(w.z, vb0a, acc0);
        acc0 = fmaf(w.w, vb1a, acc0);
        acc1 = fmaf(w.x, vt0b, acc1);
        acc1 = fmaf(w.y, vt1b, acc1);
        acc1 = fmaf(w.z, vb0b, acc1);
        acc1 = fmaf(w.w, vb1b, acc1);
        acc2 = fmaf(w.x, vt0c, acc2);
        acc2 = fmaf(w.y, vt1c, acc2);
        acc2 = fmaf(w.z, vb0c, acc2);
        acc2 = fmaf(w.w, vb1c, acc2);
        acc3 = fmaf(w.x, vt0d, acc3);
        acc3 = fmaf(w.y, vt1d, acc3);
        acc3 = fmaf(w.z, vb0d, acc3);
        acc3 = fmaf(w.w, vb1d, acc3);
    }
    float* outp = &g_agg[(size_t)bq * C_ + tid];
    outp[0]   = acc0;
    outp[64]  = acc1;
    outp[128] = acc2;
    outp[192] = acc3;
}

// ---------------------------------------------------------------------------
// GEMM: out = agg @ W^T + bias  (M=1800, N=256, K=256)
// 32x32 tiles, grid 57x8 = 456 blocks, 512 threads = 8 k-groups x 64.
// Each group: K-chunk 32 (2 BK=16 tiles, single-buffered + reg prefetch),
// 4x4 diag-pair microtile: per k-step 2 LDS.128 -> 8 FFMA2 (16 MACs / 8 floats).
// Partial-reduce buffer overlaid on the tile smem (union). Deterministic order.
// ---------------------------------------------------------------------------
#define BM 32
#define BN 32
#define BK 16
#define KG 8
#define KCH (C_ / KG)      // 32
#define NTg (KCH / BK)     // 2 tiles per group

__global__ __launch_bounds__(512, 2) void gemm_kernel(const float* __restrict__ Wm,   // (256,256) row-major
                                                      const float* __restrict__ bias,
                                                      float* __restrict__ out)        // (1800,256)
{
    __shared__ union {
        struct {
            float As[KG][BK][BM];   // 16 KB
            float Bs[KG][BK][BN];   // 16 KB
        } t;
        float Red[KG][BM * BN];     // 32 KB (overlaid; tiles dead before use)
    } sm;

    const int M = BQ_;
    int t  = threadIdx.x;       // 0..511
    int kg = t >> 6;            // k-group 0..7
    int u  = t & 63;            // lane in group
    int tm = u >> 3;            // 0..7 -> rows tm*4..+3
    int tn = u & 7;             // 0..7 -> cols tn*4..+3

    int bM = blockIdx.x * BM;
    int bN = blockIdx.y * BN;
    int koff = kg * KCH;

    // loader mapping: 128 float4 per tile -> 2 per thread (rows r1 and r1+16)
    int r1 = u >> 2;            // 0..15
    int k4 = (u & 3) * 4;       // 0,4,8,12

    const float* Ap0 = &g_agg[(size_t)(bM + r1) * C_ + koff + k4];
    const float* Ap1 = Ap0 + (size_t)16 * C_;
    const float* Bp0 = &Wm[(size_t)(bN + r1) * C_ + koff + k4];
    const float* Bp1 = Bp0 + (size_t)16 * C_;
    bool ok0 = (bM + r1) < M;
    bool ok1 = (bM + r1 + 16) < M;

    // accumulators in diagonal-pair form
    unsigned long long accd[2][2] = {{0ull, 0ull}, {0ull, 0ull}};
    unsigned long long accx[2][2] = {{0ull, 0ull}, {0ull, 0ull}};

    // load tile 0 gmem -> regs -> smem
    float4 a0 = make_float4(0.f, 0.f, 0.f, 0.f), a1 = a0;
    if (ok0) a0 = *reinterpret_cast<const float4*>(Ap0);
    if (ok1) a1 = *reinterpret_cast<const float4*>(Ap1);
    float4 b0 = *reinterpret_cast<const float4*>(Bp0);
    float4 b1 = *reinterpret_cast<const float4*>(Bp1);
    {
        float va0[4] = {a0.x, a0.y, a0.z, a0.w};
        float va1[4] = {a1.x, a1.y, a1.z, a1.w};
        float vb0[4] = {b0.x, b0.y, b0.z, b0.w};
        float vb1[4] = {b1.x, b1.y, b1.z, b1.w};
#pragma unroll
        for (int i = 0; i < 4; i++) {
            sm.t.As[kg][k4 + i][r1]      = va0[i];
            sm.t.As[kg][k4 + i][r1 + 16] = va1[i];
            sm.t.Bs[kg][k4 + i][r1]      = vb0[i];
            sm.t.Bs[kg][k4 + i][r1 + 16] = vb1[i];
        }
    }
    asm volatile("bar.sync %0, 64;" :: "r"(kg + 1) : "memory");

#pragma unroll
    for (int tile = 0; tile < NTg; tile++) {
        // prefetch next tile gmem -> regs (independent of compute)
        if (tile + 1 < NTg) {
            a0 = make_float4(0.f, 0.f, 0.f, 0.f);
            a1 = a0;
            if (ok0) a0 = *reinterpret_cast<const float4*>(Ap0 + (tile + 1) * BK);
            if (ok1) a1 = *reinterpret_cast<const float4*>(Ap1 + (tile + 1) * BK);
            b0 = *reinterpret_cast<const float4*>(Bp0 + (tile + 1) * BK);
            b1 = *reinterpret_cast<const float4*>(Bp1 + (tile + 1) * BK);
        }

        // compute BK k-steps: 2 LDS.128 -> 8 FFMA2 each
#pragma unroll
        for (int kk = 0; kk < BK; kk++) {
            ulonglong2 fa = *reinterpret_cast<const ulonglong2*>(&sm.t.As[kg][kk][tm * 4]);
            ulonglong2 fb = *reinterpret_cast<const ulonglong2*>(&sm.t.Bs[kg][kk][tn * 4]);
            unsigned long long bs0 = swap2(fb.x);
            unsigned long long bs1 = swap2(fb.y);
            ffma2(accd[0][0], fa.x, fb.x);
            ffma2(accx[0][0], fa.x, bs0);
            ffma2(accd[0][1], fa.x, fb.y);
            ffma2(accx[0][1], fa.x, bs1);
            ffma2(accd[1][0], fa.y, fb.x);
            ffma2(accx[1][0], fa.y, bs0);
            ffma2(accd[1][1], fa.y, fb.y);
            ffma2(accx[1][1], fa.y, bs1);
        }

        // single buffer: wait for group compute, overwrite, publish
        if (tile + 1 < NTg) {
            asm volatile("bar.sync %0, 64;" :: "r"(kg + 1) : "memory");
            float va0[4] = {a0.x, a0.y, a0.z, a0.w};
            float va1[4] = {a1.x, a1.y, a1.z, a1.w};
            float vb0[4] = {b0.x, b0.y, b0.z, b0.w};
            float vb1[4] = {b1.x, b1.y, b1.z, b1.w};
#pragma unroll
            for (int i = 0; i < 4; i++) {
                sm.t.As[kg][k4 + i][r1]      = va0[i];
                sm.t.As[kg][k4 + i][r1 + 16] = va1[i];
                sm.t.Bs[kg][k4 + i][r1]      = vb0[i];
                sm.t.Bs[kg][k4 + i][r1 + 16] = vb1[i];
            }
            asm volatile("bar.sync %0, 64;" :: "r"(kg + 1) : "memory");
        }
    }

    // ALL groups done with tiles before overlaying Red on them
    __syncthreads();

    // unpack diagonal pairs into plain partial layout in smem
#pragma unroll
    for (int rp = 0; rp < 2; rp++) {
#pragma unroll
        for (int jp = 0; jp < 2; jp++) {
            float2 d = *reinterpret_cast<float2*>(&accd[rp][jp]);
            float2 x = *reinterpret_cast<float2*>(&accx[rp][jp]);
            int r0 = tm * 4 + rp * 2;
            int c0 = tn * 4 + jp * 2;
            // C[r0][c0]=d.x, C[r0][c1]=x.x, C[r1][c0]=x.y, C[r1][c1]=d.y
            *reinterpret_cast<float2*>(&sm.Red[kg][r0 * BN + c0])       = make_float2(d.x, x.x);
            *reinterpret_cast<float2*>(&sm.Red[kg][(r0 + 1) * BN + c0]) = make_float2(x.y, d.y);
        }
    }
    __syncthreads();

    // reduce 8 partials + bias, store (512 threads x 2 floats = 1024 outputs)
    {
        int e   = t * 2;            // 0..1022
        int row = t >> 4;           // e / 32
        int col = (t & 15) * 2;     // e % 32
        float2 s = *reinterpret_cast<const float2*>(&sm.Red[0][e]);
#pragma unroll
        for (int g = 1; g < KG; g++) {
            float2 p = *reinterpret_cast<const float2*>(&sm.Red[g][e]);
            s.x += p.x;
            s.y += p.y;
        }
        float2 bb = *reinterpret_cast<const float2*>(&bias[bN + col]);
        s.x += bb.x;
        s.y += bb.y;
        int gm = bM + row;
        if (gm < M)
            *reinterpret_cast<float2*>(&out[(size_t)gm * C_ + bN + col]) = s;
    }
}

// ---------------------------------------------------------------------------
// launch
// inputs: 0=query (unused), 1=reference_points, 2=image_features,
//         3=lidar2img, 4=W_out, 5=b_out; output float32 (B,Q,C)
// ---------------------------------------------------------------------------
extern "C" void kernel_launch(void* const* d_in, const int* in_sizes, int n_in,
                              void* d_out, int out_size)
{
    const float* ref_pts   = (const float*)d_in[1];
    const float* feats     = (const float*)d_in[2];
    const float* lidar2img = (const float*)d_in[3];
    const float* Wm        = (const float*)d_in[4];
    const float* bias      = (const float*)d_in[5];
    float* out = (float*)d_out;

    gather_kernel<<<BQ_, 64>>>(feats, ref_pts, lidar2img);
    dim3 gg((BQ_ + BM - 1) / BM, C_ / BN);   // 57 x 8 = 456 blocks
    gemm_kernel<<<gg, 512>>>(Wm, bias, out);
}

// round 15
// speedup vs baseline: 1.2687x; 1.0494x over previous
#include <cuda_runtime.h>
#include <cstdint>

// Problem constants (fixed shapes)
#define B_  2
#define N_  6
#define Q_  900
#define C_  256
#define H_  116
#define W_  200
#define HW_ (H_ * W_)       // 23200, divisible by 4
#define EPS_ 1e-5f
#define BQ_ (B_ * Q_)       // 1800

// Scratch (no dynamic allocation allowed)
__device__ float g_agg[BQ_ * C_];   // mean-aggregated features

// Uniform-index select from float4 (s is warp-uniform -> predicated SELs)
__device__ __forceinline__ float sel4(float4 f, int s) {
    float v = f.x;
    if (s == 1) v = f.y;
    else if (s == 2) v = f.z;
    else if (s == 3) v = f.w;
    return v;
}

// packed f32x2 fma: d = a*b + d elementwise on (lo,hi) pairs in 64-bit regs
__device__ __forceinline__ void ffma2(unsigned long long& d,
                                      unsigned long long a,
                                      unsigned long long b) {
    asm("fma.rn.f32x2 %0, %1, %2, %0;" : "+l"(d) : "l"(a), "l"(b));
}

// swap the two 32-bit halves of a 64-bit pair
__device__ __forceinline__ unsigned long long swap2(unsigned long long p) {
    return (p >> 32) | (p << 32);
}

// ---------------------------------------------------------------------------
// Fused kernel: projection (threads 0..5) + bilinear gather + camera mean
// one block per (b,q); 64 threads; 4 channels/thread (tid,+64,+128,+192)
// [identical to the R6/R9/R13 best-known gather]
// ---------------------------------------------------------------------------
__global__ __launch_bounds__(64) void gather_kernel(
    const float* __restrict__ feats,     // (B,N,C,H,W)
    const float* __restrict__ ref_pts,   // (B,Q,3)
    const float* __restrict__ lidar2img) // (B,N,4,4)
{
    __shared__ float4 sw[N_];
    __shared__ int4   sb[N_];

    int bq  = blockIdx.x;
    int b   = bq / Q_;
    int q   = bq % Q_;
    int tid = threadIdx.x;

    if (tid < N_) {
        int n = tid;
        const float* rp = ref_pts + ((size_t)b * Q_ + q) * 3;
        float px = rp[0], py = rp[1], pz = rp[2];

        const float* M = lidar2img + ((size_t)b * N_ + n) * 16;
        float xc = M[0]  * px + M[1]  * py + M[2]  * pz + M[3];
        float yc = M[4]  * px + M[5]  * py + M[6]  * pz + M[7];
        float zc = M[8]  * px + M[9]  * py + M[10] * pz + M[11];

        float denom = fabsf(zc) + EPS_;
        float x2d = xc / denom;
        float y2d = yc / denom;

        float gx = x2d / (float)(W_ - 1) * 2.0f - 1.0f;
        float gy = y2d / (float)(H_ - 1) * 2.0f - 1.0f;

        bool front  = zc > EPS_;
        bool in_img = fmaxf(fabsf(gx), fabsf(gy)) <= 1.0f;
        int  valid  = (front && in_img) ? 1 : 0;
        float vv    = valid ? (1.0f / (float)N_) : 0.0f;

        float x = ((gx + 1.0f) * (float)W_ - 1.0f) * 0.5f;
        float y = ((gy + 1.0f) * (float)H_ - 1.0f) * 0.5f;
        x = fminf(fmaxf(x, -100.0f), (float)(W_ + 100));
        y = fminf(fmaxf(y, -100.0f), (float)(H_ + 100));

        float x0f = floorf(x), y0f = floorf(y);
        float wx = x - x0f, wy = y - y0f;
        int x0 = (int)x0f, y0 = (int)y0f;
        int x1 = x0 + 1,   y1 = y0 + 1;

        float v00 = (x0 >= 0 && x0 < W_ && y0 >= 0 && y0 < H_) ? 1.0f : 0.0f;
        float v10 = (x1 >= 0 && x1 < W_ && y0 >= 0 && y0 < H_) ? 1.0f : 0.0f;
        float v01 = (x0 >= 0 && x0 < W_ && y1 >= 0 && y1 < H_) ? 1.0f : 0.0f;
        float v11 = (x1 >= 0 && x1 < W_ && y1 >= 0 && y1 < H_) ? 1.0f : 0.0f;

        float4 w;
        w.x = (1.0f - wx) * (1.0f - wy) * v00 * vv;
        w.y = wx          * (1.0f - wy) * v10 * vv;
        w.z = (1.0f - wx) * wy          * v01 * vv;
        w.w = wx          * wy          * v11 * vv;

        int cx0 = min(max(x0, 0), W_ - 1);
        int cx1 = min(max(x1, 0), W_ - 1);
        int cy0 = min(max(y0, 0), H_ - 1);
        int cy1 = min(max(y1, 0), H_ - 1);

        int i0 = cy0 * W_ + cx0;
        int i1 = cy0 * W_ + cx1;
        int j0 = cy1 * W_ + cx0;

        int base_t = i0 & ~3;
        int s0 = i0 - base_t;
        int s1 = i1 - base_t;
        int base_b = j0 - s0;

        sw[n] = w;
        sb[n] = make_int4(base_t, base_b, s0 | (s1 << 8), valid);
    }
    __syncthreads();

    float acc0 = 0.0f, acc1 = 0.0f, acc2 = 0.0f, acc3 = 0.0f;
#pragma unroll
    for (int n = 0; n < N_; n++) {
        int4 ib = sb[n];
        if (!ib.w) continue;
        float4 w = sw[n];
        const float* p0 = feats + ((size_t)((b * N_ + n) * C_) + tid) * HW_;
        const float* p1 = p0 + (size_t)64  * HW_;
        const float* p2 = p0 + (size_t)128 * HW_;
        const float* p3 = p0 + (size_t)192 * HW_;

        float4 t0 = *reinterpret_cast<const float4*>(p0 + ib.x);
        float4 b0v = *reinterpret_cast<const float4*>(p0 + ib.y);
        float4 t1 = *reinterpret_cast<const float4*>(p1 + ib.x);
        float4 b1v = *reinterpret_cast<const float4*>(p1 + ib.y);
        float4 t2 = *reinterpret_cast<const float4*>(p2 + ib.x);
        float4 b2v = *reinterpret_cast<const float4*>(p2 + ib.y);
        float4 t3 = *reinterpret_cast<const float4*>(p3 + ib.x);
        float4 b3v = *reinterpret_cast<const float4*>(p3 + ib.y);

        int s0 = ib.z & 0xff;
        int s1 = ib.z >> 8;

        float vt0a = sel4(t0, s0), vb0a = sel4(b0v, s0);
        float vt0b = sel4(t1, s0), vb0b = sel4(b1v, s0);
        float vt0c = sel4(t2, s0), vb0c = sel4(b2v, s0);
        float vt0d = sel4(t3, s0), vb0d = sel4(b3v, s0);
        float vt1a, vb1a, vt1b, vb1b, vt1c, vb1c, vt1d, vb1d;
        if (s1 < 4) {
            vt1a = sel4(t0, s1);  vb1a = sel4(b0v, s1);
            vt1b = sel4(t1, s1);  vb1b = sel4(b1v, s1);
            vt1c = sel4(t2, s1);  vb1c = sel4(b2v, s1);
            vt1d = sel4(t3, s1);  vb1d = sel4(b3v, s1);
        } else {
            vt1a = __ldg(p0 + ib.x + 4);  vb1a = __ldg(p0 + ib.y + 4);
            vt1b = __ldg(p1 + ib.x + 4);  vb1b = __ldg(p1 + ib.y + 4);
            vt1c = __ldg(p2 + ib.x + 4);  vb1c = __ldg(p2 + ib.y + 4);
            vt1d = __ldg(p3 + ib.x + 4);  vb1d = __ldg(p3 + ib.y + 4);
        }
        acc0 = fmaf(w.x, vt0a, acc0);
        acc0 = fmaf(w.y, vt1a, acc0);
        acc0 = fmaf(w.z, vb0a, acc0);
        acc0 = fmaf(w.w, vb1a, acc0);
        acc1 = fmaf(w.x, vt0b, acc1);
        acc1 = fmaf(w.y, vt1b, acc1);
        acc1 = fmaf(w.z, vb0b, acc1);
        acc1 = fmaf(w.w, vb1b, acc1);
        acc2 = fmaf(w.x, vt0c, acc2);
        acc2 = fmaf(w.y, vt1c, acc2);
        acc2 = fmaf(w.z, vb0c, acc2);
        acc2 = fmaf(w.w, vb1c, acc2);
        acc3 = fmaf(w.x, vt0d, acc3);
        acc3 = fmaf(w.y, vt1d, acc3);
        acc3 = fmaf(w.z, vb0d, acc3);
        acc3 = fmaf(w.w, vb1d, acc3);
    }
    float* outp = &g_agg[(size_t)bq * C_ + tid];
    outp[0]   = acc0;
    outp[64]  = acc1;
    outp[128] = acc2;
    outp[192] = acc3;
}

// ---------------------------------------------------------------------------
// GEMM: out = agg @ W^T + bias  (M=1800, N=256, K=256)
// 32x32 tiles, grid 57x8 = 456 blocks, 256 threads = 8 warp-private k-groups.
// Each warp: K-chunk 32 (2 BK=16 tiles, single-buffered, __syncwarp only),
// 4x8 diag-pair microtile: per k-step 3 LDS.128 (48B) -> 32 MACs (1.5 B/MAC)
// as 16 FFMA2 + 4 swaps. Padded smem stride 36. Partials reduced via smem
// overlay, bias in epilogue, deterministic order.
// ---------------------------------------------------------------------------
#define BM 32
#define BN 32
#define BK 16
#define KG 8
#define KCH (C_ / KG)      // 32
#define NTg (KCH / BK)     // 2 tiles per warp
#define AST 36             // padded row stride (floats); 144B = 16 mod 128

__global__ __launch_bounds__(256, 2) void gemm_kernel(const float* __restrict__ Wm,   // (256,256) row-major
                                                      const float* __restrict__ bias,
                                                      float* __restrict__ out)        // (1800,256)
{
    __shared__ union {
        struct {
            float As[KG][BK][AST];   // 18 KB
            float Bs[KG][BK][AST];   // 18 KB
        } t;
        float Red[KG][BM * BN];      // 32 KB (overlaid; tiles dead before use)
    } sm;

    const int M = BQ_;
    int t  = threadIdx.x;       // 0..255
    int w  = t >> 5;            // warp = k-group 0..7
    int u  = t & 31;            // lane
    int tm = u >> 2;            // 0..7 -> rows tm*4..+3
    int tn = u & 3;             // 0..3 -> cols tn*8..+7

    int bM = blockIdx.x * BM;
    int bN = blockIdx.y * BN;
    int koff = w * KCH;

    // loader mapping: 128 float4 per tile, 4 per thread (rows lr+0,8,16,24)
    int lr = u >> 2;            // 0..7
    int k4 = (u & 3) * 4;       // 0,4,8,12

    const float* Abase = &g_agg[(size_t)(bM + lr) * C_ + koff + k4];
    const float* Bbase = &Wm[(size_t)(bN + lr) * C_ + koff + k4];

    // accumulators: rp in {0,1} row-pairs, jq in {0..3} col-pairs
    unsigned long long accd[2][4], accx[2][4];
#pragma unroll
    for (int i = 0; i < 2; i++)
#pragma unroll
        for (int j = 0; j < 4; j++) { accd[i][j] = 0ull; accx[i][j] = 0ull; }

    float4 a[4], b[4];
    // load tile 0 gmem -> regs
#pragma unroll
    for (int i = 0; i < 4; i++) {
        int row = lr + i * 8;
        a[i] = make_float4(0.f, 0.f, 0.f, 0.f);
        if (bM + row < M)
            a[i] = *reinterpret_cast<const float4*>(Abase + (size_t)(i * 8) * C_);
        b[i] = *reinterpret_cast<const float4*>(Bbase + (size_t)(i * 8) * C_);
    }
    // regs -> smem (transposed: As[k][row])
#pragma unroll
    for (int i = 0; i < 4; i++) {
        int row = lr + i * 8;
        float va[4] = {a[i].x, a[i].y, a[i].z, a[i].w};
        float vb[4] = {b[i].x, b[i].y, b[i].z, b[i].w};
#pragma unroll
        for (int j = 0; j < 4; j++) {
            sm.t.As[w][k4 + j][row] = va[j];
            sm.t.Bs[w][k4 + j][row] = vb[j];
        }
    }
    __syncwarp();

#pragma unroll
    for (int tile = 0; tile < NTg; tile++) {
        // prefetch next tile gmem -> regs (independent of compute)
        if (tile + 1 < NTg) {
#pragma unroll
            for (int i = 0; i < 4; i++) {
                int row = lr + i * 8;
                a[i] = make_float4(0.f, 0.f, 0.f, 0.f);
                if (bM + row < M)
                    a[i] = *reinterpret_cast<const float4*>(Abase + (size_t)(i * 8) * C_ + (tile + 1) * BK);
                b[i] = *reinterpret_cast<const float4*>(Bbase + (size_t)(i * 8) * C_ + (tile + 1) * BK);
            }
        }

        // compute BK k-steps: 3 LDS.128 -> 16 FFMA2 each
#pragma unroll
        for (int kk = 0; kk < BK; kk++) {
            ulonglong2 fa  = *reinterpret_cast<const ulonglong2*>(&sm.t.As[w][kk][tm * 4]);
            ulonglong2 fb0 = *reinterpret_cast<const ulonglong2*>(&sm.t.Bs[w][kk][tn * 8]);
            ulonglong2 fb1 = *reinterpret_cast<const ulonglong2*>(&sm.t.Bs[w][kk][tn * 8 + 4]);
            unsigned long long bq0 = fb0.x, bq1 = fb0.y, bq2 = fb1.x, bq3 = fb1.y;
            unsigned long long bs0 = swap2(bq0), bs1 = swap2(bq1);
            unsigned long long bs2 = swap2(bq2), bs3 = swap2(bq3);
            ffma2(accd[0][0], fa.x, bq0);
            ffma2(accx[0][0], fa.x, bs0);
            ffma2(accd[0][1], fa.x, bq1);
            ffma2(accx[0][1], fa.x, bs1);
            ffma2(accd[0][2], fa.x, bq2);
            ffma2(accx[0][2], fa.x, bs2);
            ffma2(accd[0][3], fa.x, bq3);
            ffma2(accx[0][3], fa.x, bs3);
            ffma2(accd[1][0], fa.y, bq0);
            ffma2(accx[1][0], fa.y, bs0);
            ffma2(accd[1][1], fa.y, bq1);
            ffma2(accx[1][1], fa.y, bs1);
            ffma2(accd[1][2], fa.y, bq2);
            ffma2(accx[1][2], fa.y, bs2);
            ffma2(accd[1][3], fa.y, bq3);
            ffma2(accx[1][3], fa.y, bs3);
        }

        // single buffer: wait for warp compute, overwrite, publish
        if (tile + 1 < NTg) {
            __syncwarp();
#pragma unroll
            for (int i = 0; i < 4; i++) {
                int row = lr + i * 8;
                float va[4] = {a[i].x, a[i].y, a[i].z, a[i].w};
                float vb[4] = {b[i].x, b[i].y, b[i].z, b[i].w};
#pragma unroll
                for (int j = 0; j < 4; j++) {
                    sm.t.As[w][k4 + j][row] = va[j];
                    sm.t.Bs[w][k4 + j][row] = vb[j];
                }
            }
            __syncwarp();
        }
    }

    // ALL warps done with tiles before overlaying Red on them
    __syncthreads();

    // unpack diagonal pairs into plain partial layout in smem
#pragma unroll
    for (int rp = 0; rp < 2; rp++) {
#pragma unroll
        for (int jq = 0; jq < 4; jq++) {
            float2 d = *reinterpret_cast<float2*>(&accd[rp][jq]);
            float2 x = *reinterpret_cast<float2*>(&accx[rp][jq]);
            int r0 = tm * 4 + rp * 2;
            int c0 = tn * 8 + jq * 2;
            // C[r0][c0]=d.x, C[r0][c1]=x.x, C[r1][c0]=x.y, C[r1][c1]=d.y
            *reinterpret_cast<float2*>(&sm.Red[w][r0 * BN + c0])       = make_float2(d.x, x.x);
            *reinterpret_cast<float2*>(&sm.Red[w][(r0 + 1) * BN + c0]) = make_float2(x.y, d.y);
        }
    }
    __syncthreads();

    // reduce 8 partials + bias, store (256 threads x 4 floats = 1024 outputs)
    {
        int e   = t * 4;            // 0..1020
        int row = t >> 3;           // e / 32
        int col = (t & 7) * 4;      // e % 32
        float4 s = *reinterpret_cast<const float4*>(&sm.Red[0][e]);
#pragma unroll
        for (int g = 1; g < KG; g++) {
            float4 p = *reinterpret_cast<const float4*>(&sm.Red[g][e]);
            s.x += p.x; s.y += p.y; s.z += p.z; s.w += p.w;
        }
        float4 bb = *reinterpret_cast<const float4*>(&bias[bN + col]);
        s.x += bb.x; s.y += bb.y; s.z += bb.z; s.w += bb.w;
        int gm = bM + row;
        if (gm < M)
            *reinterpret_cast<float4*>(&out[(size_t)gm * C_ + bN + col]) = s;
    }
}

// ---------------------------------------------------------------------------
// launch
// inputs: 0=query (unused), 1=reference_points, 2=image_features,
//         3=lidar2img, 4=W_out, 5=b_out; output float32 (B,Q,C)
// ---------------------------------------------------------------------------
extern "C" void kernel_launch(void* const* d_in, const int* in_sizes, int n_in,
                              void* d_out, int out_size)
{
    const float* ref_pts   = (const float*)d_in[1];
    const float* feats     = (const float*)d_in[2];
    const float* lidar2img = (const float*)d_in[3];
    const float* Wm        = (const float*)d_in[4];
    const float* bias      = (const float*)d_in[5];
    float* out = (float*)d_out;

    gather_kernel<<<BQ_, 64>>>(feats, ref_pts, lidar2img);
    dim3 gg((BQ_ + BM - 1) / BM, C_ / BN);   // 57 x 8 = 456 blocks
    gemm_kernel<<<gg, 256>>>(Wm, bias, out);
}